// round 6
// baseline (speedup 1.0000x reference)
#include <cuda_runtime.h>
#include <cuda_bf16.h>
#include <math.h>
#include <stdint.h>

#define BB 4
#define SS 2048
#define DD 1024
#define MT (BB*SS)   // 8192

// quant scales
#define XMAX 6.6f
#define WMAX 0.0543f
#define QKMAX 6.6f

// ---------------------------------------------------------------------------
// Scratch (device globals)
// ---------------------------------------------------------------------------
__device__ __align__(16) int8_t g_x8h[(size_t)MT*DD], g_x8l[(size_t)MT*DD];
__device__ __align__(16) int8_t g_W8h[(size_t)3*DD*DD], g_W8l[(size_t)3*DD*DD];
__device__ __align__(16) int8_t g_Q8h[(size_t)MT*DD], g_Q8l[(size_t)MT*DD];
__device__ __align__(16) int8_t g_K8h[(size_t)MT*DD], g_K8l[(size_t)MT*DD];
__device__ __align__(16) float  g_V [(size_t)MT*DD];
__device__ __align__(16) __nv_bfloat16 g_Vth[(size_t)BB*DD*SS], g_Vtl[(size_t)BB*DD*SS];
__device__ __align__(16) float  g_P [(size_t)BB*SS*SS];
__device__ __align__(16) __nv_bfloat16 g_Ph[(size_t)BB*SS*SS], g_Pl[(size_t)BB*SS*SS];

// ---------------------------------------------------------------------------
// Helpers
// ---------------------------------------------------------------------------
__device__ __forceinline__ uint32_t smem_u32(const void* p) {
    uint32_t a;
    asm("{ .reg .u64 t; cvta.to.shared.u64 t, %1; cvt.u32.u64 %0, t; }"
        : "=r"(a) : "l"(p));
    return a;
}

#define SWZ(o) ((uint32_t)(o) ^ ((((uint32_t)(o)) >> 3) & 0x70))

#define CP_ASYNC(dst, src) \
    asm volatile("cp.async.cg.shared.global [%0], [%1], 16;" \
                 :: "r"(dst), "l"(__cvta_generic_to_global(src)))
#define CP_COMMIT() asm volatile("cp.async.commit_group;")
#define CP_WAIT0()  asm volatile("cp.async.wait_group 0;")

#define LDM_X4(r, addr) \
    asm volatile("ldmatrix.sync.aligned.m8n8.x4.shared.b16 {%0,%1,%2,%3}, [%4];" \
        : "=r"((r)[0]), "=r"((r)[1]), "=r"((r)[2]), "=r"((r)[3]) : "r"(addr))

#define MMA(d, a, b0v, b1v) \
    asm volatile("mma.sync.aligned.m16n8k16.row.col.f32.bf16.bf16.f32 " \
        "{%0,%1,%2,%3}, {%4,%5,%6,%7}, {%8,%9}, {%0,%1,%2,%3};" \
        : "+f"((d)[0]), "+f"((d)[1]), "+f"((d)[2]), "+f"((d)[3]) \
        : "r"((a)[0]), "r"((a)[1]), "r"((a)[2]), "r"((a)[3]), "r"(b0v), "r"(b1v))

#define MMA_S8(d, a, b0v, b1v) \
    asm volatile("mma.sync.aligned.m16n8k32.row.col.s32.s8.s8.s32 " \
        "{%0,%1,%2,%3}, {%4,%5,%6,%7}, {%8,%9}, {%0,%1,%2,%3};" \
        : "+r"((d)[0]), "+r"((d)[1]), "+r"((d)[2]), "+r"((d)[3]) \
        : "r"((a)[0]), "r"((a)[1]), "r"((a)[2]), "r"((a)[3]), "r"(b0v), "r"(b1v))

// bf16 2-term split pack (for softmax/vtrans outputs feeding bf16 PV)
__device__ __forceinline__ uint32_t pack2(float a, float b, uint32_t& lo2) {
    __nv_bfloat16 ha = __float2bfloat16(a);
    __nv_bfloat16 hb = __float2bfloat16(b);
    __nv_bfloat16 la = __float2bfloat16(a - __bfloat162float(ha));
    __nv_bfloat16 lb = __float2bfloat16(b - __bfloat162float(hb));
    lo2 = (uint32_t)__bfloat16_as_ushort(la) | ((uint32_t)__bfloat16_as_ushort(lb) << 16);
    return (uint32_t)__bfloat16_as_ushort(ha) | ((uint32_t)__bfloat16_as_ushort(hb) << 16);
}

// int16 -> (hi8, lo8) with round-to-nearest split
__device__ __forceinline__ void quant2(float f, float inv, int8_t& h, int8_t& l) {
    int v = __float2int_rn(f * inv);
    v = max(-32512, min(32512, v));
    int vh = (v + 128) >> 8;
    h = (int8_t)vh;
    l = (int8_t)(v - (vh << 8));
}

// ---------------------------------------------------------------------------
// SMEM layout: 2 stages x 4 planes x 16KB = 128KB (shared by s8 and bf16 paths)
// ---------------------------------------------------------------------------
#define OFF_AH 0
#define OFF_AL 16384
#define OFF_BH 32768
#define OFF_BL 49152
#define STG    65536
#define SM_TOT (2*STG)

// ===========================================================================
// INT8 GEMM path (QKV + scores). Rows: 128B = K=128 int8. Chunk BK=128.
// ===========================================================================
__device__ __forceinline__ void load_chunk_s8(
    uint32_t stg,
    const int8_t* __restrict__ Ah, const int8_t* __restrict__ Al, int lda,
    const int8_t* __restrict__ Bh, const int8_t* __restrict__ Bl, int ldb,
    int k0, int tid)
{
#pragma unroll
    for (int i = 0; i < 4; ++i) {
        int u = tid + i * 256, row = u >> 3, ch = u & 7;
        uint32_t off = SWZ(row * 128 + ch * 16);
        size_t ga = (size_t)row * lda + k0 + ch * 16;
        size_t gb = (size_t)row * ldb + k0 + ch * 16;
        CP_ASYNC(stg + OFF_AH + off, Ah + ga);
        CP_ASYNC(stg + OFF_AL + off, Al + ga);
        CP_ASYNC(stg + OFF_BH + off, Bh + gb);
        CP_ASYNC(stg + OFF_BL + off, Bl + gb);
    }
}

__device__ __forceinline__ void compute_chunk_s8(
    uint32_t stg, int wm, int wn, int lane,
    int (&hh)[4][4][4], int (&mid)[4][4][4])
{
    const int rsel = lane & 15;
    const int csel = lane >> 4;
#pragma unroll
    for (int ks = 0; ks < 4; ++ks) {
        const uint32_t cb = ks * 32 + csel * 16;
        uint32_t ah[4][4], al[4][4], bh[2][4], bl[2][4];
#pragma unroll
        for (int i = 0; i < 4; ++i) {
            uint32_t off = SWZ((wm * 64 + i * 16 + rsel) * 128 + cb);
            LDM_X4(ah[i], stg + OFF_AH + off);
            LDM_X4(al[i], stg + OFF_AL + off);
        }
#pragma unroll
        for (int j2 = 0; j2 < 2; ++j2) {
            uint32_t off = SWZ((wn * 32 + j2 * 16 + rsel) * 128 + cb);
            LDM_X4(bh[j2], stg + OFF_BH + off);
            LDM_X4(bl[j2], stg + OFF_BL + off);
        }
#pragma unroll
        for (int i = 0; i < 4; ++i) {
#pragma unroll
            for (int j = 0; j < 4; ++j) {
                const int j2 = j >> 1, s = j & 1;
                MMA_S8(hh[i][j],  ah[i], bh[j2][s], bh[j2][s + 2]);
                MMA_S8(mid[i][j], ah[i], bl[j2][s], bl[j2][s + 2]);
                MMA_S8(mid[i][j], al[i], bh[j2][s], bh[j2][s + 2]);
            }
        }
    }
}

__device__ __forceinline__ void gemm_s8(
    const int8_t* __restrict__ Ah, const int8_t* __restrict__ Al, int lda,
    const int8_t* __restrict__ Bh, const int8_t* __restrict__ Bl, int ldb,
    int nCh, int (&hh)[4][4][4], int (&mid)[4][4][4], uint32_t sb, int tid)
{
    const int lane = tid & 31, w = tid >> 5;
    const int wm = w & 1, wn = w >> 1;

#pragma unroll
    for (int i = 0; i < 4; ++i)
#pragma unroll
        for (int j = 0; j < 4; ++j)
#pragma unroll
            for (int q = 0; q < 4; ++q) { hh[i][j][q] = 0; mid[i][j][q] = 0; }

    load_chunk_s8(sb, Ah, Al, lda, Bh, Bl, ldb, 0, tid);
    CP_COMMIT();

    for (int c = 0; c < nCh; ++c) {
        CP_WAIT0();
        __syncthreads();
        if (c + 1 < nCh) {
            load_chunk_s8(sb + ((c + 1) & 1) * STG, Ah, Al, lda, Bh, Bl, ldb,
                          (c + 1) * 128, tid);
            CP_COMMIT();
        }
        compute_chunk_s8(sb + (c & 1) * STG, wm, wn, lane, hh, mid);
    }
}

// ---------------------------------------------------------------------------
// 1) QKV GEMM (int8): z=0->Q8 planes, z=1->K8 planes, z=2->V fp32.
//    grid (8, 64, 3)
// ---------------------------------------------------------------------------
__global__ void __launch_bounds__(256) qkv_s8()
{
    extern __shared__ char smem[];
    const uint32_t sb = smem_u32(smem);
    const int tid = threadIdx.x, lane = tid & 31, w = tid >> 5;
    const int z = blockIdx.z;
    const int n0 = blockIdx.x * 128;
    const int m0 = blockIdx.y * 128;

    int hh[4][4][4], mid[4][4][4];
    gemm_s8(g_x8h + (size_t)m0 * DD, g_x8l + (size_t)m0 * DD, DD,
            g_W8h + (size_t)z * DD * DD + (size_t)n0 * DD,
            g_W8l + (size_t)z * DD * DD + (size_t)n0 * DD, DD,
            8, hh, mid, sb, tid);

    const int tg = lane >> 2, t4 = lane & 3;
    const int wm = w & 1, wn = w >> 1;
    const float SXW = (XMAX / 32512.f) * (WMAX / 32512.f);
    const float INVQ = 32512.f / QKMAX;

#pragma unroll
    for (int i = 0; i < 4; ++i) {
#pragma unroll
        for (int j = 0; j < 4; ++j) {
            const int r = m0 + wm * 64 + i * 16 + tg;
            const int c = n0 + wn * 32 + j * 8 + t4 * 2;
            float v[4];
#pragma unroll
            for (int q = 0; q < 4; ++q)
                v[q] = (65536.f * (float)hh[i][j][q] + 256.f * (float)mid[i][j][q]) * SXW;
            if (z == 2) {
                *(float2*)(g_V + (size_t)r * DD + c) = make_float2(v[0], v[1]);
                *(float2*)(g_V + (size_t)(r + 8) * DD + c) = make_float2(v[2], v[3]);
            } else {
                int8_t* dh = (z == 0 ? g_Q8h : g_K8h);
                int8_t* dl = (z == 0 ? g_Q8l : g_K8l);
                char2 H, L;
                quant2(v[0], INVQ, (int8_t&)H.x, (int8_t&)L.x);
                quant2(v[1], INVQ, (int8_t&)H.y, (int8_t&)L.y);
                *(char2*)(dh + (size_t)r * DD + c) = H;
                *(char2*)(dl + (size_t)r * DD + c) = L;
                quant2(v[2], INVQ, (int8_t&)H.x, (int8_t&)L.x);
                quant2(v[3], INVQ, (int8_t&)H.y, (int8_t&)L.y);
                *(char2*)(dh + (size_t)(r + 8) * DD + c) = H;
                *(char2*)(dl + (size_t)(r + 8) * DD + c) = L;
            }
        }
    }
}

// ---------------------------------------------------------------------------
// 2) Scores (int8): P = scale * Q @ K^T, causal tiles only. grid (136, 4)
// ---------------------------------------------------------------------------
__global__ void __launch_bounds__(256) scores_s8()
{
    const int t = blockIdx.x, b = blockIdx.y;
    int it = (int)floorf((sqrtf(8.f * (float)t + 1.f) - 1.f) * 0.5f);
    while ((it + 1) * (it + 2) / 2 <= t) ++it;
    while (it * (it + 1) / 2 > t) --it;
    const int jt = t - it * (it + 1) / 2;

    extern __shared__ char smem[];
    const uint32_t sb = smem_u32(smem);
    const int tid = threadIdx.x, lane = tid & 31, w = tid >> 5;

    int hh[4][4][4], mid[4][4][4];
    gemm_s8(g_Q8h + ((size_t)b * SS + it * 128) * DD,
            g_Q8l + ((size_t)b * SS + it * 128) * DD, DD,
            g_K8h + ((size_t)b * SS + jt * 128) * DD,
            g_K8l + ((size_t)b * SS + jt * 128) * DD, DD,
            8, hh, mid, sb, tid);

    const int tg = lane >> 2, t4 = lane & 3;
    const int wm = w & 1, wn = w >> 1;
    const float SC = (QKMAX / 32512.f) * (QKMAX / 32512.f) * 0.03125f;

#pragma unroll
    for (int i = 0; i < 4; ++i) {
#pragma unroll
        for (int j = 0; j < 4; ++j) {
            const int r = it * 128 + wm * 64 + i * 16 + tg;
            const int c = jt * 128 + wn * 32 + j * 8 + t4 * 2;
            float v[4];
#pragma unroll
            for (int q = 0; q < 4; ++q)
                v[q] = (65536.f * (float)hh[i][j][q] + 256.f * (float)mid[i][j][q]) * SC;
            float* base = g_P + (size_t)b * SS * SS;
            *(float2*)(base + (size_t)r * SS + c) = make_float2(v[0], v[1]);
            *(float2*)(base + (size_t)(r + 8) * SS + c) = make_float2(v[2], v[3]);
        }
    }
}

// ===========================================================================
// bf16 GEMM path (PV only) — unchanged from R5.
// ===========================================================================
__device__ __forceinline__ void load_chunk_bf(
    uint32_t stg,
    const __nv_bfloat16* __restrict__ Ah, const __nv_bfloat16* __restrict__ Al, int lda,
    const __nv_bfloat16* __restrict__ Bh, const __nv_bfloat16* __restrict__ Bl, int ldb,
    int k0, int tid)
{
#pragma unroll
    for (int i = 0; i < 4; ++i) {
        int u = tid + i * 256, row = u >> 3, ch = u & 7;
        uint32_t off = SWZ(row * 128 + ch * 16);
        size_t ga = (size_t)row * lda + k0 + ch * 8;
        size_t gb = (size_t)row * ldb + k0 + ch * 8;
        CP_ASYNC(stg + OFF_AH + off, Ah + ga);
        CP_ASYNC(stg + OFF_AL + off, Al + ga);
        CP_ASYNC(stg + OFF_BH + off, Bh + gb);
        CP_ASYNC(stg + OFF_BL + off, Bl + gb);
    }
}

__device__ __forceinline__ void compute_chunk_bf(
    uint32_t stg, int wm, int wn, int lane, float (&acc)[4][4][4])
{
    const int rsel = lane & 15;
    const int csel = lane >> 4;
#pragma unroll
    for (int ks = 0; ks < 4; ++ks) {
        uint32_t ah[4][4], al[4][4], bh[2][4], bl[2][4];
#pragma unroll
        for (int i = 0; i < 4; ++i) {
            uint32_t off = SWZ((wm * 64 + i * 16 + rsel) * 128 + (ks * 2 + csel) * 16);
            LDM_X4(ah[i], stg + OFF_AH + off);
            LDM_X4(al[i], stg + OFF_AL + off);
        }
#pragma unroll
        for (int j2 = 0; j2 < 2; ++j2) {
            uint32_t off = SWZ((wn * 32 + j2 * 16 + rsel) * 128 + (ks * 2 + csel) * 16);
            LDM_X4(bh[j2], stg + OFF_BH + off);
            LDM_X4(bl[j2], stg + OFF_BL + off);
        }
#pragma unroll
        for (int i = 0; i < 4; ++i) {
#pragma unroll
            for (int j = 0; j < 4; ++j) {
                const int j2 = j >> 1, s = j & 1;
                MMA(acc[i][j], ah[i], bh[j2][s], bh[j2][s + 2]);
                MMA(acc[i][j], ah[i], bl[j2][s], bl[j2][s + 2]);
                MMA(acc[i][j], al[i], bh[j2][s], bh[j2][s + 2]);
            }
        }
    }
}

__device__ __forceinline__ void gemm_hmma(
    const __nv_bfloat16* __restrict__ Ah, const __nv_bfloat16* __restrict__ Al, int lda,
    const __nv_bfloat16* __restrict__ Bh, const __nv_bfloat16* __restrict__ Bl, int ldb,
    int nCh, float (&acc)[4][4][4], uint32_t sb, int tid)
{
    const int lane = tid & 31, w = tid >> 5;
    const int wm = w & 1, wn = w >> 1;

#pragma unroll
    for (int i = 0; i < 4; ++i)
#pragma unroll
        for (int j = 0; j < 4; ++j)
#pragma unroll
            for (int q = 0; q < 4; ++q) acc[i][j][q] = 0.f;

    load_chunk_bf(sb, Ah, Al, lda, Bh, Bl, ldb, 0, tid);
    CP_COMMIT();

    for (int c = 0; c < nCh; ++c) {
        CP_WAIT0();
        __syncthreads();
        if (c + 1 < nCh) {
            load_chunk_bf(sb + ((c + 1) & 1) * STG, Ah, Al, lda, Bh, Bl, ldb,
                          (c + 1) * 64, tid);
            CP_COMMIT();
        }
        compute_chunk_bf(sb + (c & 1) * STG, wm, wn, lane, acc);
    }
}

// ---------------------------------------------------------------------------
// 3) PV: O = P @ V (bf16 split). Heavy row-blocks first. grid (8, 16, 4)
// ---------------------------------------------------------------------------
__global__ void __launch_bounds__(256) pv_gemm(float* __restrict__ out)
{
    extern __shared__ char smem[];
    const uint32_t sb = smem_u32(smem);
    const int tid = threadIdx.x, lane = tid & 31, w = tid >> 5;
    const int n0 = blockIdx.x * 128;
    const int it = 15 - blockIdx.y;   // heavy-first
    const int b = blockIdx.z;

    float acc[4][4][4];
    gemm_hmma(g_Ph + ((size_t)b * SS + it * 128) * SS,
              g_Pl + ((size_t)b * SS + it * 128) * SS, SS,
              g_Vth + ((size_t)b * DD + n0) * SS,
              g_Vtl + ((size_t)b * DD + n0) * SS, SS,
              (it + 1) * 2, acc, sb, tid);

    const int tg = lane >> 2, t4 = lane & 3;
    const int wm = w & 1, wn = w >> 1;
#pragma unroll
    for (int i = 0; i < 4; ++i) {
#pragma unroll
        for (int j = 0; j < 4; ++j) {
            const size_t r = (size_t)b * SS + it * 128 + wm * 64 + i * 16 + tg;
            const int c = n0 + wn * 32 + j * 8 + t4 * 2;
            *(float2*)(out + r * DD + c) = make_float2(acc[i][j][0], acc[i][j][1]);
            *(float2*)(out + (r + 8) * DD + c) = make_float2(acc[i][j][2], acc[i][j][3]);
        }
    }
}

// ---------------------------------------------------------------------------
// Prep: quantize x to int8 hi/lo planes. grid 8192, block 256
// ---------------------------------------------------------------------------
__global__ void __launch_bounds__(256) quant_x_kernel(const float* __restrict__ in)
{
    size_t i = (size_t)blockIdx.x * 256 + threadIdx.x;
    float4 v = ((const float4*)in)[i];
    const float inv = 32512.f / XMAX;
    char4 H, L;
    quant2(v.x, inv, (int8_t&)H.x, (int8_t&)L.x);
    quant2(v.y, inv, (int8_t&)H.y, (int8_t&)L.y);
    quant2(v.z, inv, (int8_t&)H.z, (int8_t&)L.z);
    quant2(v.w, inv, (int8_t&)H.w, (int8_t&)L.w);
    ((char4*)g_x8h)[i] = H;
    ((char4*)g_x8l)[i] = L;
}

// ---------------------------------------------------------------------------
// Prep: transpose + quantize W. grid (32, 32, 3), block (32, 8)
// ---------------------------------------------------------------------------
__global__ void __launch_bounds__(256) prep_w8_kernel(
    const float* __restrict__ WQ, const float* __restrict__ WK,
    const float* __restrict__ WV)
{
    __shared__ float t[32][33];
    const float* W = (blockIdx.z == 0) ? WQ : (blockIdx.z == 1) ? WK : WV;
    const int n0 = blockIdx.x * 32, k0 = blockIdx.y * 32;
    const int tx = threadIdx.x, ty = threadIdx.y;
    const float inv = 32512.f / WMAX;
#pragma unroll
    for (int j = 0; j < 32; j += 8)
        t[ty + j][tx] = W[(size_t)(k0 + ty + j) * DD + n0 + tx];
    __syncthreads();
    int8_t* oh = g_W8h + (size_t)blockIdx.z * DD * DD;
    int8_t* ol = g_W8l + (size_t)blockIdx.z * DD * DD;
#pragma unroll
    for (int j = 0; j < 32; j += 8) {
        int8_t h, l;
        quant2(t[tx][ty + j], inv, h, l);
        size_t o = (size_t)(n0 + ty + j) * DD + k0 + tx;
        oh[o] = h;
        ol[o] = l;
    }
}

// ---------------------------------------------------------------------------
// V transpose + bf16 split: Vt[b][d][s] = V[b*S+s][d]. grid (32, 64, 4)
// ---------------------------------------------------------------------------
__global__ void __launch_bounds__(256) vtrans_kernel()
{
    __shared__ float t[32][33];
    const int b = blockIdx.z;
    const int d0 = blockIdx.x * 32, s0 = blockIdx.y * 32;
    const int tx = threadIdx.x, ty = threadIdx.y;
#pragma unroll
    for (int j = 0; j < 32; j += 8)
        t[ty + j][tx] = g_V[((size_t)b * SS + s0 + ty + j) * DD + d0 + tx];
    __syncthreads();
#pragma unroll
    for (int j = 0; j < 32; j += 8) {
        float v = t[tx][ty + j];
        __nv_bfloat16 h = __float2bfloat16(v);
        __nv_bfloat16 l = __float2bfloat16(v - __bfloat162float(h));
        size_t o = ((size_t)b * DD + d0 + ty + j) * SS + s0 + tx;
        g_Vth[o] = h;
        g_Vtl[o] = l;
    }
}

// ---------------------------------------------------------------------------
// Softmax: fp32 P row -> bf16 hi/lo P, zero-padded to 128-tile edge.
// grid 8192, block 256
// ---------------------------------------------------------------------------
__global__ void __launch_bounds__(256) softmax_kernel()
{
    const int row = blockIdx.x;
    const int b = row >> 11;
    const int i = row & 2047;
    const float* p = g_P + ((size_t)b * SS + i) * SS;
    __nv_bfloat16* ph = g_Ph + ((size_t)b * SS + i) * SS;
    __nv_bfloat16* pl = g_Pl + ((size_t)b * SS + i) * SS;
    const int L = i + 1;
    const int E = ((i >> 7) + 1) << 7;
    const int tid = threadIdx.x;
    const int base = tid * 8;

    __shared__ float red[256];

    float vals[8];
    {
        float4 v0 = ((const float4*)p)[tid * 2];
        float4 v1 = ((const float4*)p)[tid * 2 + 1];
        vals[0] = v0.x; vals[1] = v0.y; vals[2] = v0.z; vals[3] = v0.w;
        vals[4] = v1.x; vals[5] = v1.y; vals[6] = v1.z; vals[7] = v1.w;
    }
    float m = -INFINITY;
#pragma unroll
    for (int u = 0; u < 8; u++) {
        if (base + u >= L) vals[u] = -INFINITY;
        m = fmaxf(m, vals[u]);
    }
    red[tid] = m;
    __syncthreads();
    for (int s = 128; s > 0; s >>= 1) {
        if (tid < s) red[tid] = fmaxf(red[tid], red[tid + s]);
        __syncthreads();
    }
    m = red[0];
    __syncthreads();

    float sum = 0.f;
#pragma unroll
    for (int u = 0; u < 8; u++) {
        vals[u] = (base + u < L) ? expf(vals[u] - m) : 0.f;
        sum += vals[u];
    }
    red[tid] = sum;
    __syncthreads();
    for (int s = 128; s > 0; s >>= 1) {
        if (tid < s) red[tid] += red[tid + s];
        __syncthreads();
    }
    const float inv = 1.f / red[0];

    if (base < E) {
        uint4 H, L4;
        H.x = pack2(vals[0] * inv, vals[1] * inv, L4.x);
        H.y = pack2(vals[2] * inv, vals[3] * inv, L4.y);
        H.z = pack2(vals[4] * inv, vals[5] * inv, L4.z);
        H.w = pack2(vals[6] * inv, vals[7] * inv, L4.w);
        *(uint4*)(ph + base) = H;
        *(uint4*)(pl + base) = L4;
    }
}

// ---------------------------------------------------------------------------
extern "C" void kernel_launch(void* const* d_in, const int* in_sizes, int n_in,
                              void* d_out, int out_size)
{
    (void)in_sizes; (void)n_in; (void)out_size;
    const float* x  = (const float*)d_in[0];
    const float* WQ = (const float*)d_in[1];
    const float* WK = (const float*)d_in[2];
    const float* WV = (const float*)d_in[3];
    float* out = (float*)d_out;

    cudaFuncSetAttribute(qkv_s8,    cudaFuncAttributeMaxDynamicSharedMemorySize, SM_TOT);
    cudaFuncSetAttribute(scores_s8, cudaFuncAttributeMaxDynamicSharedMemorySize, SM_TOT);
    cudaFuncSetAttribute(pv_gemm,   cudaFuncAttributeMaxDynamicSharedMemorySize, SM_TOT);

    quant_x_kernel<<<8192, 256>>>(x);
    prep_w8_kernel<<<dim3(32, 32, 3), dim3(32, 8)>>>(WQ, WK, WV);
    qkv_s8<<<dim3(8, 64, 3), 256, SM_TOT>>>();
    vtrans_kernel<<<dim3(32, 64, 4), dim3(32, 8)>>>();
    scores_s8<<<dim3(136, 4), 256, SM_TOT>>>();
    softmax_kernel<<<8192, 256>>>();
    pv_gemm<<<dim3(8, 16, 4), 256, SM_TOT>>>(out);
}

// round 7
// speedup vs baseline: 3.1382x; 3.1382x over previous
#include <cuda_runtime.h>
#include <cuda_fp16.h>
#include <math.h>
#include <stdint.h>

#define BB 4
#define SS 2048
#define DD 1024
#define MT (BB*SS)   // 8192

// ---------------------------------------------------------------------------
// Scratch (device globals). A-side operands: hi plane only. B-side: hi+lo.
// ---------------------------------------------------------------------------
__device__ __align__(16) __half g_xh [(size_t)MT*DD];                 // A of QKV
__device__ __align__(16) __half g_Wth[(size_t)3*DD*DD], g_Wtl[(size_t)3*DD*DD];
__device__ __align__(16) __half g_Qh [(size_t)MT*DD];                 // A of scores
__device__ __align__(16) __half g_Kh [(size_t)MT*DD], g_Kl[(size_t)MT*DD];
__device__ __align__(16) float  g_V  [(size_t)MT*DD];
__device__ __align__(16) __half g_Vth[(size_t)BB*DD*SS], g_Vtl[(size_t)BB*DD*SS];
__device__ __align__(16) float  g_P  [(size_t)BB*SS*SS];
__device__ __align__(16) __half g_Ph [(size_t)BB*SS*SS];              // A of PV

// ---------------------------------------------------------------------------
// Helpers
// ---------------------------------------------------------------------------
__device__ __forceinline__ uint32_t smem_u32(const void* p) {
    uint32_t a;
    asm("{ .reg .u64 t; cvta.to.shared.u64 t, %1; cvt.u32.u64 %0, t; }"
        : "=r"(a) : "l"(p));
    return a;
}

#define SWZ(o) ((uint32_t)(o) ^ ((((uint32_t)(o)) >> 3) & 0x70))

#define CP_ASYNC(dst, src) \
    asm volatile("cp.async.cg.shared.global [%0], [%1], 16;" \
                 :: "r"(dst), "l"(__cvta_generic_to_global(src)))
#define CP_COMMIT() asm volatile("cp.async.commit_group;")
#define CP_WAIT0()  asm volatile("cp.async.wait_group 0;")

#define LDM_X4(r, addr) \
    asm volatile("ldmatrix.sync.aligned.m8n8.x4.shared.b16 {%0,%1,%2,%3}, [%4];" \
        : "=r"((r)[0]), "=r"((r)[1]), "=r"((r)[2]), "=r"((r)[3]) : "r"(addr))

#define MMA_F16(d, a, b0v, b1v) \
    asm volatile("mma.sync.aligned.m16n8k16.row.col.f32.f16.f16.f32 " \
        "{%0,%1,%2,%3}, {%4,%5,%6,%7}, {%8,%9}, {%0,%1,%2,%3};" \
        : "+f"((d)[0]), "+f"((d)[1]), "+f"((d)[2]), "+f"((d)[3]) \
        : "r"((a)[0]), "r"((a)[1]), "r"((a)[2]), "r"((a)[3]), "r"(b0v), "r"(b1v))

// pack two floats into one half2 register (round-to-nearest)
__device__ __forceinline__ uint32_t packh2(float a, float b) {
    __half2 h = __floats2half2_rn(a, b);
    return *(uint32_t*)&h;
}
// fp16 hi/lo split of a pair
__device__ __forceinline__ void split2(float a, float b, uint32_t& hi, uint32_t& lo) {
    __half ha = __float2half_rn(a), hb = __float2half_rn(b);
    __half la = __float2half_rn(a - __half2float(ha));
    __half lb = __float2half_rn(b - __half2float(hb));
    hi = (uint32_t)*(uint16_t*)&ha | ((uint32_t)*(uint16_t*)&hb << 16);
    lo = (uint32_t)*(uint16_t*)&la | ((uint32_t)*(uint16_t*)&lb << 16);
}

// ---------------------------------------------------------------------------
// SMEM: stage = A(16KB) + BH(16KB) + BL(16KB) = 48KB; 2 stages = 96KB
// -> 2 CTAs/SM (regs capped at 128 via launch_bounds)
// ---------------------------------------------------------------------------
#define OFF_A  0
#define OFF_BH 16384
#define OFF_BL 32768
#define STG    49152
#define SM_TOT (2*STG)   // 98304

// ---------------------------------------------------------------------------
// Load one BK=64 chunk (3 planes) via cp.async. 12 x 16B per thread.
// ---------------------------------------------------------------------------
__device__ __forceinline__ void load_chunk(
    uint32_t stg,
    const __half* __restrict__ A, int lda,
    const __half* __restrict__ Bh, const __half* __restrict__ Bl, int ldb,
    int k0, int tid)
{
#pragma unroll
    for (int i = 0; i < 4; ++i) {
        int u = tid + i * 256, row = u >> 3, ch = u & 7;
        uint32_t off = SWZ(row * 128 + ch * 16);
        size_t ga = (size_t)row * lda + k0 + ch * 8;
        size_t gb = (size_t)row * ldb + k0 + ch * 8;
        CP_ASYNC(stg + OFF_A  + off, A  + ga);
        CP_ASYNC(stg + OFF_BH + off, Bh + gb);
        CP_ASYNC(stg + OFF_BL + off, Bl + gb);
    }
}

// ---------------------------------------------------------------------------
// Compute one BK=64 chunk: warp tile 64x32, 2-term fp16: acc += A*(Bh+Bl)
// ---------------------------------------------------------------------------
__device__ __forceinline__ void compute_chunk(
    uint32_t stg, int wm, int wn, int lane, float (&acc)[4][4][4])
{
    const int rsel = lane & 15;
    const int csel = lane >> 4;
#pragma unroll
    for (int ks = 0; ks < 4; ++ks) {
        uint32_t ah[4][4], bh[2][4], bl[2][4];
#pragma unroll
        for (int i = 0; i < 4; ++i) {
            uint32_t off = SWZ((wm * 64 + i * 16 + rsel) * 128 + (ks * 2 + csel) * 16);
            LDM_X4(ah[i], stg + OFF_A + off);
        }
#pragma unroll
        for (int j2 = 0; j2 < 2; ++j2) {
            uint32_t off = SWZ((wn * 32 + j2 * 16 + rsel) * 128 + (ks * 2 + csel) * 16);
            LDM_X4(bh[j2], stg + OFF_BH + off);
            LDM_X4(bl[j2], stg + OFF_BL + off);
        }
#pragma unroll
        for (int i = 0; i < 4; ++i) {
#pragma unroll
            for (int j = 0; j < 4; ++j) {
                const int j2 = j >> 1, s = j & 1;
                MMA_F16(acc[i][j], ah[i], bh[j2][s], bh[j2][s + 2]);
                MMA_F16(acc[i][j], ah[i], bl[j2][s], bl[j2][s + 2]);
            }
        }
    }
}

// ---------------------------------------------------------------------------
// GEMM mainloop: single __syncthreads per chunk.
// ---------------------------------------------------------------------------
__device__ __forceinline__ void gemm_f16(
    const __half* __restrict__ A, int lda,
    const __half* __restrict__ Bh, const __half* __restrict__ Bl, int ldb,
    int nCh, float (&acc)[4][4][4], uint32_t sb, int tid)
{
    const int lane = tid & 31, w = tid >> 5;
    const int wm = w & 1, wn = w >> 1;

#pragma unroll
    for (int i = 0; i < 4; ++i)
#pragma unroll
        for (int j = 0; j < 4; ++j)
#pragma unroll
            for (int q = 0; q < 4; ++q) acc[i][j][q] = 0.f;

    load_chunk(sb, A, lda, Bh, Bl, ldb, 0, tid);
    CP_COMMIT();

    for (int c = 0; c < nCh; ++c) {
        CP_WAIT0();
        __syncthreads();
        if (c + 1 < nCh) {
            load_chunk(sb + ((c + 1) & 1) * STG, A, lda, Bh, Bl, ldb,
                       (c + 1) * 64, tid);
            CP_COMMIT();
        }
        compute_chunk(sb + (c & 1) * STG, wm, wn, lane, acc);
    }
}

// ---------------------------------------------------------------------------
// 1) QKV GEMM: z=0->Q (fp16 hi only), z=1->K (fp16 split), z=2->V (fp32).
//    grid (8, 64, 3)
// ---------------------------------------------------------------------------
__global__ void __launch_bounds__(256, 2) qkv_gemm()
{
    extern __shared__ char smem[];
    const uint32_t sb = smem_u32(smem);
    const int tid = threadIdx.x, lane = tid & 31, w = tid >> 5;
    const int z = blockIdx.z;
    const int n0 = blockIdx.x * 128;
    const int m0 = blockIdx.y * 128;

    float acc[4][4][4];
    gemm_f16(g_xh + (size_t)m0 * DD, DD,
             g_Wth + (size_t)z * DD * DD + (size_t)n0 * DD,
             g_Wtl + (size_t)z * DD * DD + (size_t)n0 * DD, DD,
             16, acc, sb, tid);

    const int tg = lane >> 2, t4 = lane & 3;
    const int wm = w & 1, wn = w >> 1;
#pragma unroll
    for (int i = 0; i < 4; ++i) {
#pragma unroll
        for (int j = 0; j < 4; ++j) {
            const int r = m0 + wm * 64 + i * 16 + tg;
            const int c = n0 + wn * 32 + j * 8 + t4 * 2;
            if (z == 2) {
                *(float2*)(g_V + (size_t)r * DD + c) =
                    make_float2(acc[i][j][0], acc[i][j][1]);
                *(float2*)(g_V + (size_t)(r + 8) * DD + c) =
                    make_float2(acc[i][j][2], acc[i][j][3]);
            } else if (z == 0) {
                *(uint32_t*)(g_Qh + (size_t)r * DD + c) =
                    packh2(acc[i][j][0], acc[i][j][1]);
                *(uint32_t*)(g_Qh + (size_t)(r + 8) * DD + c) =
                    packh2(acc[i][j][2], acc[i][j][3]);
            } else {
                uint32_t hi, lo;
                split2(acc[i][j][0], acc[i][j][1], hi, lo);
                *(uint32_t*)(g_Kh + (size_t)r * DD + c) = hi;
                *(uint32_t*)(g_Kl + (size_t)r * DD + c) = lo;
                split2(acc[i][j][2], acc[i][j][3], hi, lo);
                *(uint32_t*)(g_Kh + (size_t)(r + 8) * DD + c) = hi;
                *(uint32_t*)(g_Kl + (size_t)(r + 8) * DD + c) = lo;
            }
        }
    }
}

// ---------------------------------------------------------------------------
// 2) Scores: P = scale * Q @ K^T, causal tiles only. grid (136, 4)
// ---------------------------------------------------------------------------
__global__ void __launch_bounds__(256, 2) scores_gemm()
{
    const int t = blockIdx.x, b = blockIdx.y;
    int it = (int)floorf((sqrtf(8.f * (float)t + 1.f) - 1.f) * 0.5f);
    while ((it + 1) * (it + 2) / 2 <= t) ++it;
    while (it * (it + 1) / 2 > t) --it;
    const int jt = t - it * (it + 1) / 2;

    extern __shared__ char smem[];
    const uint32_t sb = smem_u32(smem);
    const int tid = threadIdx.x, lane = tid & 31, w = tid >> 5;

    float acc[4][4][4];
    gemm_f16(g_Qh + ((size_t)b * SS + it * 128) * DD, DD,
             g_Kh + ((size_t)b * SS + jt * 128) * DD,
             g_Kl + ((size_t)b * SS + jt * 128) * DD, DD,
             16, acc, sb, tid);

    const int tg = lane >> 2, t4 = lane & 3;
    const int wm = w & 1, wn = w >> 1;
    const float scale = 0.03125f;  // 1/sqrt(1024)
#pragma unroll
    for (int i = 0; i < 4; ++i) {
#pragma unroll
        for (int j = 0; j < 4; ++j) {
            const int r = it * 128 + wm * 64 + i * 16 + tg;
            const int c = jt * 128 + wn * 32 + j * 8 + t4 * 2;
            float* base = g_P + (size_t)b * SS * SS;
            *(float2*)(base + (size_t)r * SS + c) =
                make_float2(acc[i][j][0] * scale, acc[i][j][1] * scale);
            *(float2*)(base + (size_t)(r + 8) * SS + c) =
                make_float2(acc[i][j][2] * scale, acc[i][j][3] * scale);
        }
    }
}

// ---------------------------------------------------------------------------
// 3) PV: O = P @ V. Heavy row-blocks first. grid (8, 16, 4)
// ---------------------------------------------------------------------------
__global__ void __launch_bounds__(256, 2) pv_gemm(float* __restrict__ out)
{
    extern __shared__ char smem[];
    const uint32_t sb = smem_u32(smem);
    const int tid = threadIdx.x, lane = tid & 31, w = tid >> 5;
    const int n0 = blockIdx.x * 128;
    const int it = 15 - blockIdx.y;   // heavy-first
    const int b = blockIdx.z;

    float acc[4][4][4];
    gemm_f16(g_Ph + ((size_t)b * SS + it * 128) * SS, SS,
             g_Vth + ((size_t)b * DD + n0) * SS,
             g_Vtl + ((size_t)b * DD + n0) * SS, SS,
             (it + 1) * 2, acc, sb, tid);

    const int tg = lane >> 2, t4 = lane & 3;
    const int wm = w & 1, wn = w >> 1;
#pragma unroll
    for (int i = 0; i < 4; ++i) {
#pragma unroll
        for (int j = 0; j < 4; ++j) {
            const size_t r = (size_t)b * SS + it * 128 + wm * 64 + i * 16 + tg;
            const int c = n0 + wn * 32 + j * 8 + t4 * 2;
            *(float2*)(out + r * DD + c) = make_float2(acc[i][j][0], acc[i][j][1]);
            *(float2*)(out + (r + 8) * DD + c) = make_float2(acc[i][j][2], acc[i][j][3]);
        }
    }
}

// ---------------------------------------------------------------------------
// Prep: x -> fp16 hi plane. grid 8192, block 256 (4 floats/thread)
// ---------------------------------------------------------------------------
__global__ void __launch_bounds__(256) prep_x_kernel(const float* __restrict__ in)
{
    size_t i = (size_t)blockIdx.x * 256 + threadIdx.x;
    float4 v = ((const float4*)in)[i];
    uint2 H;
    H.x = packh2(v.x, v.y);
    H.y = packh2(v.z, v.w);
    ((uint2*)g_xh)[i] = H;
}

// ---------------------------------------------------------------------------
// Prep: transpose + fp16 split W. grid (32, 32, 3), block (32, 8)
// ---------------------------------------------------------------------------
__global__ void __launch_bounds__(256) prep_w_kernel(
    const float* __restrict__ WQ, const float* __restrict__ WK,
    const float* __restrict__ WV)
{
    __shared__ float t[32][33];
    const float* W = (blockIdx.z == 0) ? WQ : (blockIdx.z == 1) ? WK : WV;
    const int n0 = blockIdx.x * 32, k0 = blockIdx.y * 32;
    const int tx = threadIdx.x, ty = threadIdx.y;
#pragma unroll
    for (int j = 0; j < 32; j += 8)
        t[ty + j][tx] = W[(size_t)(k0 + ty + j) * DD + n0 + tx];
    __syncthreads();
    __half* oh = g_Wth + (size_t)blockIdx.z * DD * DD;
    __half* ol = g_Wtl + (size_t)blockIdx.z * DD * DD;
#pragma unroll
    for (int j = 0; j < 32; j += 8) {
        float v = t[tx][ty + j];
        __half h = __float2half_rn(v);
        __half l = __float2half_rn(v - __half2float(h));
        size_t o = (size_t)(n0 + ty + j) * DD + k0 + tx;
        oh[o] = h;
        ol[o] = l;
    }
}

// ---------------------------------------------------------------------------
// V transpose + fp16 split. grid (32, 64, 4), block (32, 8)
// ---------------------------------------------------------------------------
__global__ void __launch_bounds__(256) vtrans_kernel()
{
    __shared__ float t[32][33];
    const int b = blockIdx.z;
    const int d0 = blockIdx.x * 32, s0 = blockIdx.y * 32;
    const int tx = threadIdx.x, ty = threadIdx.y;
#pragma unroll
    for (int j = 0; j < 32; j += 8)
        t[ty + j][tx] = g_V[((size_t)b * SS + s0 + ty + j) * DD + d0 + tx];
    __syncthreads();
#pragma unroll
    for (int j = 0; j < 32; j += 8) {
        float v = t[tx][ty + j];
        __half h = __float2half_rn(v);
        __half l = __float2half_rn(v - __half2float(h));
        size_t o = ((size_t)b * DD + d0 + ty + j) * SS + s0 + tx;
        g_Vth[o] = h;
        g_Vtl[o] = l;
    }
}

// ---------------------------------------------------------------------------
// Softmax: fp32 P row -> fp16 hi plane, zero-padded to 128-tile edge.
// grid 8192, block 256
// ---------------------------------------------------------------------------
__global__ void __launch_bounds__(256) softmax_kernel()
{
    const int row = blockIdx.x;
    const int b = row >> 11;
    const int i = row & 2047;
    const float* p = g_P + ((size_t)b * SS + i) * SS;
    __half* ph = g_Ph + ((size_t)b * SS + i) * SS;
    const int L = i + 1;
    const int E = ((i >> 7) + 1) << 7;
    const int tid = threadIdx.x;
    const int base = tid * 8;

    __shared__ float red[256];

    float vals[8];
    {
        float4 v0 = ((const float4*)p)[tid * 2];
        float4 v1 = ((const float4*)p)[tid * 2 + 1];
        vals[0] = v0.x; vals[1] = v0.y; vals[2] = v0.z; vals[3] = v0.w;
        vals[4] = v1.x; vals[5] = v1.y; vals[6] = v1.z; vals[7] = v1.w;
    }
    float m = -INFINITY;
#pragma unroll
    for (int u = 0; u < 8; u++) {
        if (base + u >= L) vals[u] = -INFINITY;
        m = fmaxf(m, vals[u]);
    }
    red[tid] = m;
    __syncthreads();
    for (int s = 128; s > 0; s >>= 1) {
        if (tid < s) red[tid] = fmaxf(red[tid], red[tid + s]);
        __syncthreads();
    }
    m = red[0];
    __syncthreads();

    float sum = 0.f;
#pragma unroll
    for (int u = 0; u < 8; u++) {
        vals[u] = (base + u < L) ? expf(vals[u] - m) : 0.f;
        sum += vals[u];
    }
    red[tid] = sum;
    __syncthreads();
    for (int s = 128; s > 0; s >>= 1) {
        if (tid < s) red[tid] += red[tid + s];
        __syncthreads();
    }
    const float inv = 1.f / red[0];

    if (base < E) {
        uint4 H;
        H.x = packh2(vals[0] * inv, vals[1] * inv);
        H.y = packh2(vals[2] * inv, vals[3] * inv);
        H.z = packh2(vals[4] * inv, vals[5] * inv);
        H.w = packh2(vals[6] * inv, vals[7] * inv);
        *(uint4*)(ph + base) = H;
    }
}

// ---------------------------------------------------------------------------
extern "C" void kernel_launch(void* const* d_in, const int* in_sizes, int n_in,
                              void* d_out, int out_size)
{
    (void)in_sizes; (void)n_in; (void)out_size;
    const float* x  = (const float*)d_in[0];
    const float* WQ = (const float*)d_in[1];
    const float* WK = (const float*)d_in[2];
    const float* WV = (const float*)d_in[3];
    float* out = (float*)d_out;

    cudaFuncSetAttribute(qkv_gemm,    cudaFuncAttributeMaxDynamicSharedMemorySize, SM_TOT);
    cudaFuncSetAttribute(scores_gemm, cudaFuncAttributeMaxDynamicSharedMemorySize, SM_TOT);
    cudaFuncSetAttribute(pv_gemm,     cudaFuncAttributeMaxDynamicSharedMemorySize, SM_TOT);

    prep_x_kernel<<<8192, 256>>>(x);
    prep_w_kernel<<<dim3(32, 32, 3), dim3(32, 8)>>>(WQ, WK, WV);
    qkv_gemm<<<dim3(8, 64, 3), 256, SM_TOT>>>();
    vtrans_kernel<<<dim3(32, 64, 4), dim3(32, 8)>>>();
    scores_gemm<<<dim3(136, 4), 256, SM_TOT>>>();
    softmax_kernel<<<8192, 256>>>();
    pv_gemm<<<dim3(8, 16, 4), 256, SM_TOT>>>(out);
}